// round 12
// baseline (speedup 1.0000x reference)
#include <cuda_runtime.h>
#include <math.h>

#define A_ 10
#define B_ 1024
#define Y_ 94
#define R_ 256
#define H_ 128
#define G_ 768
#define T_ 50
#define IN_ 350
#define FS_ 0.1f

#define BTILE 74
#define NTILES 14      // 14*74 = 1036 >= 1024
#define ROWPAD 80      // 16 warps ; 5 m16 tiles
#define NTHREADS 512
#define ES 356         // enc row stride (float4-aligned)
#define DS 132         // d/e row stride

#define NK8_I 44       // gi k8 tiles: 12 (y, padded 96) + 32 (h)
#define NK8_H 32       // gh k8 tiles

typedef unsigned long long ull;

__device__ __forceinline__ ull pack2(float x, float y) {
    ull r; asm("mov.b64 %0, {%1, %2};" : "=l"(r) : "f"(x), "f"(y)); return r;
}
__device__ __forceinline__ unsigned f2tf(float f) {
    unsigned r; asm("cvt.rna.tf32.f32 %0, %1;" : "=r"(r) : "f"(f)); return r;
}
__device__ __forceinline__ float tf32f(float f) { return __uint_as_float(f2tf(f)); }
__device__ __forceinline__ void mma8(float* d, const unsigned* A, unsigned b0, unsigned b1) {
    asm volatile("mma.sync.aligned.m16n8k8.row.col.f32.tf32.tf32.f32 "
        "{%0,%1,%2,%3}, {%4,%5,%6,%7}, {%8,%9}, {%0,%1,%2,%3};"
        : "+f"(d[0]), "+f"(d[1]), "+f"(d[2]), "+f"(d[3])
        : "r"(A[0]), "r"(A[1]), "r"(A[2]), "r"(A[3]), "r"(b0), "r"(b1));
}
// fast gates: MUFU-based sigmoid/tanh (~2^-11 rel err; same scale as tf32 noise)
__device__ __forceinline__ float fsigmoid(float x) {
    float e; asm("ex2.approx.f32 %0, %1;" : "=f"(e) : "f"(-1.4426950408889634f * x));
    float r; asm("rcp.approx.f32 %0, %1;" : "=f"(r) : "f"(1.f + e));
    return r;
}
__device__ __forceinline__ float ftanh(float x) {
    float r; asm("tanh.approx.f32 %0, %1;" : "=f"(r) : "f"(x));
    return r;
}

// scratch (no cudaMalloc allowed)
__device__ __align__(16) float g_h[A_ * B_ * R_];
__device__ __align__(16) float g_Wim[A_ * 32 * NK8_I * 3 * 64];  // gi B-frags, tf32
__device__ __align__(16) float g_Whm[A_ * 32 * NK8_H * 3 * 64];  // gh B-frags, tf32
__device__ __align__(16) float g_d1m[A_ * 16 * 32 * 64];         // d1 B-frags, tf32
__device__ __align__(16) float g_d2m[A_ * 16 * 16 * 64];         // d2 B-frags, tf32
__device__ double g_acc[3];

// ---- single prep kernel: init + all weight repacks ----
__global__ void prep_kernel(const float* __restrict__ W_ih, const float* __restrict__ W_hh,
                            const float* __restrict__ d1w,  const float* __restrict__ d2w) {
    const int stride = gridDim.x * blockDim.x;
    const int tid0 = blockIdx.x * blockDim.x + threadIdx.x;

    for (int i = tid0; i < A_ * B_ * R_; i += stride) g_h[i] = 0.f;
    if (tid0 < 3) g_acc[tid0] = 0.0;

    const int NWI = A_ * 32 * NK8_I * 3 * 64;
    for (int i = tid0; i < NWI; i += stride) {
        int s = i & 1, l = (i >> 1) & 31;
        int r = i >> 6;
        int g = r % 3; r /= 3;
        int k8 = r % NK8_I; r /= NK8_I;
        int c = r % 32; int a = r / 32;
        int j = g * 256 + c * 8 + (l >> 2);
        float v = 0.f;
        if (k8 < 12) {
            int k = k8 * 8 + (l & 3) + 4 * s;
            if (k < Y_) v = W_ih[((size_t)a * G_ + j) * IN_ + k];
        } else {
            int k = Y_ + (k8 - 12) * 8 + (l & 3) + 4 * s;
            v = W_ih[((size_t)a * G_ + j) * IN_ + k];
        }
        g_Wim[i] = __uint_as_float(f2tf(v));
    }
    const int NWH = A_ * 32 * NK8_H * 3 * 64;
    for (int i = tid0; i < NWH; i += stride) {
        int s = i & 1, l = (i >> 1) & 31;
        int r = i >> 6;
        int g = r % 3; r /= 3;
        int k8 = r % NK8_H; r /= NK8_H;
        int c = r % 32; int a = r / 32;
        int j = g * 256 + c * 8 + (l >> 2);
        int k = k8 * 8 + (l & 3) + 4 * s;
        g_Whm[i] = __uint_as_float(f2tf(W_hh[((size_t)a * G_ + j) * R_ + k]));
    }
    const int ND1 = A_ * 16 * 32 * 64;
    for (int i = tid0; i < ND1; i += stride) {
        int s = i & 1, l = (i >> 1) & 31;
        int r = i >> 6;
        int k8 = r % 32; r /= 32;
        int c = r % 16; int a = r / 16;
        int j = c * 8 + (l >> 2);
        int k = k8 * 8 + (l & 3) + 4 * s;
        g_d1m[i] = __uint_as_float(f2tf(d1w[((size_t)a * H_ + j) * R_ + k]));
    }
    const int ND2 = A_ * 16 * 16 * 64;
    for (int i = tid0; i < ND2; i += stride) {
        int s = i & 1, l = (i >> 1) & 31;
        int r = i >> 6;
        int k8 = r % 16; r /= 16;
        int c = r % 16; int a = r / 16;
        int j = c * 8 + (l >> 2);
        int k = k8 * 8 + (l & 3) + 4 * s;
        g_d2m[i] = __uint_as_float(f2tf(d2w[((size_t)a * H_ + j) * H_ + k]));
    }
}

// ep term is RNN-independent: fully parallel over (t, a, b)
__global__ void ep_kernel(const float* __restrict__ states) {
    int idx = blockIdx.x * blockDim.x + threadIdx.x;
    double e = 0.0;
    if (idx < T_ * A_ * B_) {
        int t = idx / (A_ * B_);
        int r = idx - t * (A_ * B_);
        int a = r >> 10;
        int b = r & 1023;
        size_t base = (((size_t)t * A_ + a) * B_ + b) * Y_ + 4 * a;
        float f0 = states[base + 0], f1 = states[base + 1];
        float f2 = states[base + 2], f3 = states[base + 3];
        size_t base1 = base + (size_t)A_ * B_ * Y_;
        float g0 = states[base1 + 0], g1 = states[base1 + 1];
        float d0 = f0 + f2 * FS_ - g0;
        float d1 = f1 + f3 * FS_ - g1;
        e = sqrt((double)d0 * d0 + (double)d1 * d1);
    }
    #pragma unroll
    for (int o = 16; o; o >>= 1) e += __shfl_down_sync(0xffffffffu, e, o);
    if ((threadIdx.x & 31) == 0) atomicAdd(&g_acc[1], e);
}

__global__ __launch_bounds__(NTHREADS) void step_kernel(
    const float* __restrict__ states,
    const float* __restrict__ b_ih, const float* __restrict__ b_hh,
    const float* __restrict__ d1b,  const float* __restrict__ d2b,
    const float* __restrict__ mw,   const float* __restrict__ mb,
    const float* __restrict__ sw,   const float* __restrict__ sb,
    int t)
{
    extern __shared__ float sm[];
    float* enc_s = sm;                         // ROWPAD*ES  [y(96 padded)|h(256)], tf32-rounded
    float* d_s   = enc_s + ROWPAD * ES;        // ROWPAD*DS
    float* e_s   = d_s   + ROWPAD * DS;        // ROWPAD*DS
    float* ms_s  = e_s   + ROWPAD * DS;        // ROWPAD*4

    const int a     = blockIdx.y;
    const int row0  = blockIdx.x * BTILE;
    const int nrows = min(BTILE, B_ - row0);
    const int tid   = threadIdx.x;
    const int tx    = tid & 31;
    const int ty    = tid >> 5;     // warp 0..15
    const int lane  = tx;
    const int tg    = lane & 3;     // thread-in-group
    const int gid   = lane >> 2;    // row within tile

    // ---- stage enc = [y | 0 0 | h], tf32-rounded (mma A operand) ----
    const float* hg = g_h + ((size_t)a * B_ + row0) * R_;
    for (int i = tid; i < ROWPAD * R_; i += NTHREADS) {
        int r = i >> 8, k = i & 255;
        enc_s[r * ES + 96 + k] = (r < nrows) ? tf32f(hg[(size_t)r * R_ + k]) : 0.f;
    }
    const float* yg = states + (((size_t)t * A_ + a) * B_ + row0) * Y_;
    for (int i = tid; i < ROWPAD * 96; i += NTHREADS) {
        int r = i / 96, k = i - r * 96;
        enc_s[r * ES + k] = (r < nrows && k < Y_) ? tf32f(yg[(size_t)r * Y_ + k]) : 0.f;
    }
    __syncthreads();

    // ---- D1 via mma: units = 5 m16 x 16 c = 80, 5/warp ----
    {
        #pragma unroll 1
        for (int u = 0; u < 5; u++) {
            int unit = ty + 16 * u;          // 0..79
            int m0 = (unit % 5) * 16;
            int c  = unit / 5;               // 0..15
            const float2* Wb = reinterpret_cast<const float2*>(
                g_d1m + ((size_t)(a * 16 + c) * 32) * 64);
            float acc[4];
            {
                float2 bv = *reinterpret_cast<const float2*>(&d1b[a * H_ + c * 8 + 2 * tg]);
                acc[0] = bv.x; acc[1] = bv.y; acc[2] = bv.x; acc[3] = bv.y;
            }
            float2 w = Wb[lane];
            for (int k8 = 0; k8 < 32; k8++) {
                float2 wn = Wb[((k8 < 31) ? k8 + 1 : 31) * 32 + lane];
                int kc = 96 + k8 * 8 + tg;
                unsigned A0[4];
                A0[0] = __float_as_uint(enc_s[(m0 + gid) * ES + kc]);
                A0[1] = __float_as_uint(enc_s[(m0 + gid + 8) * ES + kc]);
                A0[2] = __float_as_uint(enc_s[(m0 + gid) * ES + kc + 4]);
                A0[3] = __float_as_uint(enc_s[(m0 + gid + 8) * ES + kc + 4]);
                mma8(acc, A0, __float_as_uint(w.x), __float_as_uint(w.y));
                w = wn;
            }
            int jb = c * 8 + 2 * tg;
            #pragma unroll
            for (int half = 0; half < 2; half++) {
                int r = m0 + gid + 8 * half;
                float v0 = tf32f(fmaxf(acc[2 * half], 0.f));
                float v1 = tf32f(fmaxf(acc[2 * half + 1], 0.f));
                *reinterpret_cast<ull*>(&d_s[r * DS + jb]) = pack2(v0, v1);
            }
        }
    }
    __syncthreads();

    // ---- D2 via mma: K=16 k8, A from d_s ----
    {
        #pragma unroll 1
        for (int u = 0; u < 5; u++) {
            int unit = ty + 16 * u;
            int m0 = (unit % 5) * 16;
            int c  = unit / 5;
            const float2* Wb = reinterpret_cast<const float2*>(
                g_d2m + ((size_t)(a * 16 + c) * 16) * 64);
            float acc[4];
            {
                float2 bv = *reinterpret_cast<const float2*>(&d2b[a * H_ + c * 8 + 2 * tg]);
                acc[0] = bv.x; acc[1] = bv.y; acc[2] = bv.x; acc[3] = bv.y;
            }
            float2 w = Wb[lane];
            for (int k8 = 0; k8 < 16; k8++) {
                float2 wn = Wb[((k8 < 15) ? k8 + 1 : 15) * 32 + lane];
                int kc = k8 * 8 + tg;
                unsigned A0[4];
                A0[0] = __float_as_uint(d_s[(m0 + gid) * DS + kc]);
                A0[1] = __float_as_uint(d_s[(m0 + gid + 8) * DS + kc]);
                A0[2] = __float_as_uint(d_s[(m0 + gid) * DS + kc + 4]);
                A0[3] = __float_as_uint(d_s[(m0 + gid + 8) * DS + kc + 4]);
                mma8(acc, A0, __float_as_uint(w.x), __float_as_uint(w.y));
                w = wn;
            }
            int jb = c * 8 + 2 * tg;
            #pragma unroll
            for (int half = 0; half < 2; half++) {
                int r = m0 + gid + 8 * half;
                float v0 = fmaxf(acc[2 * half], 0.f);
                float v1 = fmaxf(acc[2 * half + 1], 0.f);
                *reinterpret_cast<ull*>(&e_s[r * DS + jb]) = pack2(v0, v1);
            }
        }
    }
    __syncthreads();

    // ---- mean / std heads (exact math; softplus feeds log) ----
    for (int task = tid; task < nrows * 4; task += NTHREADS) {
        int r = task >> 2, o = task & 3;
        const float* W = (o < 2) ? (mw + ((size_t)a * 2 + o) * H_)
                                 : (sw + ((size_t)a * 2 + (o - 2)) * H_);
        float acc = (o < 2) ? mb[a * 2 + o] : sb[a * 2 + o - 2];
        for (int k = 0; k < H_; k++) acc += e_s[r * DS + k] * W[k];
        if (o >= 2)
            acc = fmaxf(acc, 0.f) + log1pf(expf(-fabsf(acc)));
        ms_s[r * 4 + o] = acc;
    }
    __syncthreads();

    // ---- per-row NLL + ev ----
    {
        double lsum = 0.0, esum = 0.0;
        if (tid < nrows) {
            int b = row0 + tid;
            size_t xb = (((size_t)(t + 1) * A_ + a) * B_ + b) * Y_ + 4 * a;
            float x0 = states[xb + 2], x1 = states[xb + 3];
            float m0 = ms_s[tid * 4 + 0], m1 = ms_s[tid * 4 + 1];
            float s0 = ms_s[tid * 4 + 2], s1 = ms_s[tid * 4 + 3];
            float z0 = (x0 - m0) / s0, z1 = (x1 - m1) / s1;
            const double L2PI = 1.8378770664093453;
            lsum = 0.5 * ((double)(z0 * z0) + (double)(z1 * z1)
                 + 2.0 * ((double)logf(s0) + (double)logf(s1)) + 2.0 * L2PI);
            float dm0 = m0 - x0, dm1 = m1 - x1;
            esum = sqrt((double)dm0 * dm0 + (double)dm1 * dm1);
        }
        #pragma unroll
        for (int o = 16; o; o >>= 1) {
            lsum += __shfl_down_sync(0xffffffffu, lsum, o);
            esum += __shfl_down_sync(0xffffffffu, esum, o);
        }
        if ((tid & 31) == 0) {
            atomicAdd(&g_acc[0], lsum);
            atomicAdd(&g_acc[2], esum);
        }
    }

    // ---- GRU via tf32 mma (R9 structure: dist-1 rotation) ----
    {
        #pragma unroll 1
        for (int u = 0; u < 6; u++) {
            int unit = ty + 16 * u;          // 0..95
            int mg = unit >> 5;              // 0..2
            int c  = unit & 31;
            int m0 = mg * 32;
            const bool two = (mg < 2);
            int j0 = c * 8;
            const float2* Wib = reinterpret_cast<const float2*>(
                g_Wim + ((size_t)(a * 32 + c) * NK8_I * 3) * 64);
            const float2* Whb = reinterpret_cast<const float2*>(
                g_Whm + ((size_t)(a * 32 + c) * NK8_H * 3) * 64);

            float acc0[6][4], acc1[6][4];
            {
                int jb = j0 + 2 * tg;
                float2 bv[6];
                bv[0] = *reinterpret_cast<const float2*>(&b_ih[a * G_ + jb]);
                bv[1] = *reinterpret_cast<const float2*>(&b_ih[a * G_ + 256 + jb]);
                bv[2] = *reinterpret_cast<const float2*>(&b_ih[a * G_ + 512 + jb]);
                bv[3] = *reinterpret_cast<const float2*>(&b_hh[a * G_ + jb]);
                bv[4] = *reinterpret_cast<const float2*>(&b_hh[a * G_ + 256 + jb]);
                bv[5] = *reinterpret_cast<const float2*>(&b_hh[a * G_ + 512 + jb]);
                #pragma unroll
                for (int g = 0; g < 6; g++) {
                    acc0[g][0] = bv[g].x; acc0[g][1] = bv[g].y;
                    acc0[g][2] = bv[g].x; acc0[g][3] = bv[g].y;
                    acc1[g][0] = bv[g].x; acc1[g][1] = bv[g].y;
                    acc1[g][2] = bv[g].x; acc1[g][3] = bv[g].y;
                }
            }

            // ---- y region: 12 k8, 3 gi gates ----
            {
                float2 w[3], wn[3];
                #pragma unroll
                for (int g = 0; g < 3; g++) w[g] = Wib[g * 32 + lane];
                for (int k8 = 0; k8 < 12; k8++) {
                    int k8n = (k8 < 11) ? k8 + 1 : 11;
                    #pragma unroll
                    for (int g = 0; g < 3; g++) wn[g] = Wib[(k8n * 3 + g) * 32 + lane];
                    int kc = k8 * 8 + tg;
                    unsigned A0[4];
                    A0[0] = __float_as_uint(enc_s[(m0 + gid) * ES + kc]);
                    A0[1] = __float_as_uint(enc_s[(m0 + gid + 8) * ES + kc]);
                    A0[2] = __float_as_uint(enc_s[(m0 + gid) * ES + kc + 4]);
                    A0[3] = __float_as_uint(enc_s[(m0 + gid + 8) * ES + kc + 4]);
                    #pragma unroll
                    for (int g = 0; g < 3; g++)
                        mma8(acc0[g], A0, __float_as_uint(w[g].x), __float_as_uint(w[g].y));
                    if (two) {
                        unsigned A1[4];
                        A1[0] = __float_as_uint(enc_s[(m0 + 16 + gid) * ES + kc]);
                        A1[1] = __float_as_uint(enc_s[(m0 + 24 + gid) * ES + kc]);
                        A1[2] = __float_as_uint(enc_s[(m0 + 16 + gid) * ES + kc + 4]);
                        A1[3] = __float_as_uint(enc_s[(m0 + 24 + gid) * ES + kc + 4]);
                        #pragma unroll
                        for (int g = 0; g < 3; g++)
                            mma8(acc1[g], A1, __float_as_uint(w[g].x), __float_as_uint(w[g].y));
                    }
                    #pragma unroll
                    for (int g = 0; g < 3; g++) w[g] = wn[g];
                }
            }

            // ---- h region: 32 k8, all 6 gates share the A fragment ----
            {
                float2 w[6], wn[6];
                #pragma unroll
                for (int g = 0; g < 3; g++) {
                    w[g]     = Wib[(12 * 3 + g) * 32 + lane];
                    w[3 + g] = Whb[g * 32 + lane];
                }
                for (int k8 = 0; k8 < 32; k8++) {
                    int k8n = (k8 < 31) ? k8 + 1 : 31;
                    #pragma unroll
                    for (int g = 0; g < 3; g++) {
                        wn[g]     = Wib[((12 + k8n) * 3 + g) * 32 + lane];
                        wn[3 + g] = Whb[(k8n * 3 + g) * 32 + lane];
                    }
                    int kc = 96 + k8 * 8 + tg;
                    unsigned A0[4];
                    A0[0] = __float_as_uint(enc_s[(m0 + gid) * ES + kc]);
                    A0[1] = __float_as_uint(enc_s[(m0 + gid + 8) * ES + kc]);
                    A0[2] = __float_as_uint(enc_s[(m0 + gid) * ES + kc + 4]);
                    A0[3] = __float_as_uint(enc_s[(m0 + gid + 8) * ES + kc + 4]);
                    #pragma unroll
                    for (int g = 0; g < 6; g++)
                        mma8(acc0[g], A0, __float_as_uint(w[g].x), __float_as_uint(w[g].y));
                    if (two) {
                        unsigned A1[4];
                        A1[0] = __float_as_uint(enc_s[(m0 + 16 + gid) * ES + kc]);
                        A1[1] = __float_as_uint(enc_s[(m0 + 24 + gid) * ES + kc]);
                        A1[2] = __float_as_uint(enc_s[(m0 + 16 + gid) * ES + kc + 4]);
                        A1[3] = __float_as_uint(enc_s[(m0 + 24 + gid) * ES + kc + 4]);
                        #pragma unroll
                        for (int g = 0; g < 6; g++)
                            mma8(acc1[g], A1, __float_as_uint(w[g].x), __float_as_uint(w[g].y));
                    }
                    #pragma unroll
                    for (int g = 0; g < 6; g++) w[g] = wn[g];
                }
            }

            // ---- epilogue: fast gates + h update ----
            #pragma unroll
            for (int tile = 0; tile < 2; tile++) {
                if (tile == 1 && !two) break;
                float (*ac)[4] = tile ? acc1 : acc0;
                int mt = m0 + 16 * tile;
                #pragma unroll
                for (int half = 0; half < 2; half++) {
                    int r = mt + gid + 8 * half;
                    int e0 = 2 * half, e1 = e0 + 1;
                    if (r < nrows) {
                        int jb = j0 + 2 * tg;
                        float* hrow = &g_h[((size_t)a * B_ + row0 + r) * R_ + jb];
                        float2 hold = *reinterpret_cast<const float2*>(hrow);
                        float rg0 = fsigmoid(ac[0][e0] + ac[3][e0]);
                        float rg1 = fsigmoid(ac[0][e1] + ac[3][e1]);
                        float zg0 = fsigmoid(ac[1][e0] + ac[4][e0]);
                        float zg1 = fsigmoid(ac[1][e1] + ac[4][e1]);
                        float ng0 = ftanh(ac[2][e0] + rg0 * ac[5][e0]);
                        float ng1 = ftanh(ac[2][e1] + rg1 * ac[5][e1]);
                        float h0 = (1.f - zg0) * ng0 + zg0 * hold.x;
                        float h1 = (1.f - zg1) * ng1 + zg1 * hold.y;
                        *reinterpret_cast<ull*>(hrow) = pack2(h0, h1);
                    }
                }
            }
        }
    }
}

__global__ void final_kernel(float* out) {
    if (threadIdx.x == 0) {
        const double denom = (double)T_ * A_;
        out[0] = (float)(g_acc[0] / denom);
        out[1] = (float)(g_acc[1] / denom);
        out[2] = (float)(g_acc[2] / denom);
    }
}

extern "C" void kernel_launch(void* const* d_in, const int* in_sizes, int n_in,
                              void* d_out, int out_size) {
    const float* states = (const float*)d_in[0];
    const float* W_ih   = (const float*)d_in[1];
    const float* W_hh   = (const float*)d_in[2];
    const float* b_ih   = (const float*)d_in[3];
    const float* b_hh   = (const float*)d_in[4];
    const float* d1w    = (const float*)d_in[5];
    const float* d1b    = (const float*)d_in[6];
    const float* d2w    = (const float*)d_in[7];
    const float* d2b    = (const float*)d_in[8];
    const float* mw     = (const float*)d_in[9];
    const float* mb     = (const float*)d_in[10];
    const float* sw     = (const float*)d_in[11];
    const float* sb     = (const float*)d_in[12];
    float* out = (float*)d_out;

    const size_t SMEM = (size_t)ROWPAD * (ES + DS + DS + 4) * sizeof(float); // 199,680 B
    cudaFuncSetAttribute(step_kernel, cudaFuncAttributeMaxDynamicSharedMemorySize, (int)SMEM);

    prep_kernel<<<1024, 256>>>(W_ih, W_hh, d1w, d2w);
    ep_kernel<<<(T_ * A_ * B_ + 255) / 256, 256>>>(states);

    dim3 grid(NTILES, A_);
    for (int t = 0; t < T_; t++) {
        step_kernel<<<grid, NTHREADS, SMEM>>>(states, b_ih, b_hh,
                                              d1b, d2b, mw, mb, sw, sb, t);
    }
    final_kernel<<<1, 32>>>(out);
}

// round 13
// speedup vs baseline: 1.4339x; 1.4339x over previous
#include <cuda_runtime.h>
#include <math.h>

#define A_ 10
#define B_ 1024
#define Y_ 94
#define R_ 256
#define H_ 128
#define G_ 768
#define T_ 50
#define IN_ 350
#define FS_ 0.1f

#define BTILE 74
#define NTILES 14      // 14*74 = 1036 >= 1024
#define ROWPAD 80      // 16 warps * RT 5 rows ; 5 m16 tiles
#define RT 5
#define NTHREADS 512
#define ES 356         // enc row stride (float4-aligned)
#define DS 132         // d/e row stride

#define NK8_I 44       // gi k8 tiles: 12 (y, padded 96) + 32 (h)
#define NK8_H 32       // gh k8 tiles

typedef unsigned long long ull;

__device__ __forceinline__ ull pack2(float x, float y) {
    ull r; asm("mov.b64 %0, {%1, %2};" : "=l"(r) : "f"(x), "f"(y)); return r;
}
__device__ __forceinline__ ull dup2(float x) {
    ull r; asm("mov.b64 %0, {%1, %1};" : "=l"(r) : "f"(x)); return r;
}
__device__ __forceinline__ ull fma2(ull a, ull b, ull c) {
    ull d; asm("fma.rn.f32x2 %0, %1, %2, %3;" : "=l"(d) : "l"(a), "l"(b), "l"(c)); return d;
}
__device__ __forceinline__ float2 unpk2(ull v) {
    float2 f; asm("mov.b64 {%0, %1}, %2;" : "=f"(f.x), "=f"(f.y) : "l"(v)); return f;
}
__device__ __forceinline__ unsigned f2tf(float f) {
    unsigned r; asm("cvt.rna.tf32.f32 %0, %1;" : "=r"(r) : "f"(f)); return r;
}
__device__ __forceinline__ float tf32f(float f) { return __uint_as_float(f2tf(f)); }
__device__ __forceinline__ void mma8(float* d, const unsigned* A, unsigned b0, unsigned b1) {
    asm volatile("mma.sync.aligned.m16n8k8.row.col.f32.tf32.tf32.f32 "
        "{%0,%1,%2,%3}, {%4,%5,%6,%7}, {%8,%9}, {%0,%1,%2,%3};"
        : "+f"(d[0]), "+f"(d[1]), "+f"(d[2]), "+f"(d[3])
        : "r"(A[0]), "r"(A[1]), "r"(A[2]), "r"(A[3]), "r"(b0), "r"(b1));
}
// fast gates: MUFU-based sigmoid/tanh (~2^-11 rel err; same scale as tf32 noise)
__device__ __forceinline__ float fsigmoid(float x) {
    float e; asm("ex2.approx.f32 %0, %1;" : "=f"(e) : "f"(-1.4426950408889634f * x));
    float r; asm("rcp.approx.f32 %0, %1;" : "=f"(r) : "f"(1.f + e));
    return r;
}
__device__ __forceinline__ float ftanh(float x) {
    float r; asm("tanh.approx.f32 %0, %1;" : "=f"(r) : "f"(x));
    return r;
}

// scratch (no cudaMalloc allowed)
__device__ __align__(16) float g_h[A_ * B_ * R_];
__device__ __align__(16) float g_Wim[A_ * 32 * NK8_I * 3 * 64];  // gi B-frags, tf32
__device__ __align__(16) float g_Whm[A_ * 32 * NK8_H * 3 * 64];  // gh B-frags, tf32
__device__ __align__(16) float g_d1T[A_ * R_ * H_];              // [a][k][j]
__device__ __align__(16) float g_d2T[A_ * H_ * H_];              // [a][k][j]
__device__ double g_acc[3];

// ---- single prep kernel: init + all weight repacks ----
__global__ void prep_kernel(const float* __restrict__ W_ih, const float* __restrict__ W_hh,
                            const float* __restrict__ d1w,  const float* __restrict__ d2w) {
    const int stride = gridDim.x * blockDim.x;
    const int tid0 = blockIdx.x * blockDim.x + threadIdx.x;

    for (int i = tid0; i < A_ * B_ * R_; i += stride) g_h[i] = 0.f;
    if (tid0 < 3) g_acc[tid0] = 0.0;

    // gi weights -> per-(c, k8, gate) 8x8 B-fragments: lane l holds (b0,b1) at +2l
    const int NWI = A_ * 32 * NK8_I * 3 * 64;
    for (int i = tid0; i < NWI; i += stride) {
        int s = i & 1, l = (i >> 1) & 31;
        int r = i >> 6;
        int g = r % 3; r /= 3;
        int k8 = r % NK8_I; r /= NK8_I;
        int c = r % 32; int a = r / 32;
        int j = g * 256 + c * 8 + (l >> 2);
        float v = 0.f;
        if (k8 < 12) {
            int k = k8 * 8 + (l & 3) + 4 * s;
            if (k < Y_) v = W_ih[((size_t)a * G_ + j) * IN_ + k];
        } else {
            int k = Y_ + (k8 - 12) * 8 + (l & 3) + 4 * s;
            v = W_ih[((size_t)a * G_ + j) * IN_ + k];
        }
        g_Wim[i] = __uint_as_float(f2tf(v));
    }
    // gh weights
    const int NWH = A_ * 32 * NK8_H * 3 * 64;
    for (int i = tid0; i < NWH; i += stride) {
        int s = i & 1, l = (i >> 1) & 31;
        int r = i >> 6;
        int g = r % 3; r /= 3;
        int k8 = r % NK8_H; r /= NK8_H;
        int c = r % 32; int a = r / 32;
        int j = g * 256 + c * 8 + (l >> 2);
        int k = k8 * 8 + (l & 3) + 4 * s;
        g_Whm[i] = __uint_as_float(f2tf(W_hh[((size_t)a * G_ + j) * R_ + k]));
    }
    // d-net transposes (fp32 FFMA2 path)
    for (int i = tid0; i < A_ * R_ * H_; i += stride) {
        int j = i % H_;
        int r = i / H_;
        int k = r % R_;
        int a = r / R_;
        g_d1T[i] = d1w[((size_t)a * H_ + j) * R_ + k];
    }
    for (int i = tid0; i < A_ * H_ * H_; i += stride) {
        int j = i % H_;
        int r = i / H_;
        int k = r % H_;
        int a = r / H_;
        g_d2T[i] = d2w[((size_t)a * H_ + j) * H_ + k];
    }
}

// ep term is RNN-independent: fully parallel over (t, a, b)
__global__ void ep_kernel(const float* __restrict__ states) {
    int idx = blockIdx.x * blockDim.x + threadIdx.x;
    double e = 0.0;
    if (idx < T_ * A_ * B_) {
        int t = idx / (A_ * B_);
        int r = idx - t * (A_ * B_);
        int a = r >> 10;
        int b = r & 1023;
        size_t base = (((size_t)t * A_ + a) * B_ + b) * Y_ + 4 * a;
        float f0 = states[base + 0], f1 = states[base + 1];
        float f2 = states[base + 2], f3 = states[base + 3];
        size_t base1 = base + (size_t)A_ * B_ * Y_;
        float g0 = states[base1 + 0], g1 = states[base1 + 1];
        float d0 = f0 + f2 * FS_ - g0;
        float d1 = f1 + f3 * FS_ - g1;
        e = sqrt((double)d0 * d0 + (double)d1 * d1);
    }
    #pragma unroll
    for (int o = 16; o; o >>= 1) e += __shfl_down_sync(0xffffffffu, e, o);
    if ((threadIdx.x & 31) == 0) atomicAdd(&g_acc[1], e);
}

__global__ __launch_bounds__(NTHREADS) void step_kernel(
    const float* __restrict__ states,
    const float* __restrict__ b_ih, const float* __restrict__ b_hh,
    const float* __restrict__ d1b,  const float* __restrict__ d2b,
    const float* __restrict__ mw,   const float* __restrict__ mb,
    const float* __restrict__ sw,   const float* __restrict__ sb,
    int t)
{
    extern __shared__ float sm[];
    float* enc_s = sm;                         // ROWPAD*ES  [y(96 padded)|h(256)], tf32-rounded
    float* d_s   = enc_s + ROWPAD * ES;        // ROWPAD*DS
    float* e_s   = d_s   + ROWPAD * DS;        // ROWPAD*DS
    float* ms_s  = e_s   + ROWPAD * DS;        // ROWPAD*4

    const int a     = blockIdx.y;
    const int row0  = blockIdx.x * BTILE;
    const int nrows = min(BTILE, B_ - row0);
    const int tid   = threadIdx.x;
    const int tx    = tid & 31;
    const int ty    = tid >> 5;     // warp 0..15
    const int cp    = 2 * tx;

    // ---- stage enc = [y | 0 0 | h], tf32-rounded (mma A operand) ----
    const float* hg = g_h + ((size_t)a * B_ + row0) * R_;
    for (int i = tid; i < ROWPAD * R_; i += NTHREADS) {
        int r = i >> 8, k = i & 255;
        enc_s[r * ES + 96 + k] = (r < nrows) ? tf32f(hg[(size_t)r * R_ + k]) : 0.f;
    }
    const float* yg = states + (((size_t)t * A_ + a) * B_ + row0) * Y_;
    for (int i = tid; i < ROWPAD * 96; i += NTHREADS) {
        int r = i / 96, k = i - r * 96;
        enc_s[r * ES + k] = (r < nrows && k < Y_) ? tf32f(yg[(size_t)r * Y_ + k]) : 0.f;
    }
    __syncthreads();

    // ---- D1 (FFMA2): col-pairs (cp, cp+1) and (cp+64, cp+65), rows ty+16i ----
    {
        ull acc[RT][2];
        {
            ull b0 = *reinterpret_cast<const ull*>(&d1b[a * H_ + cp]);
            ull b1 = *reinterpret_cast<const ull*>(&d1b[a * H_ + cp + 64]);
            #pragma unroll
            for (int i = 0; i < RT; i++) { acc[i][0] = b0; acc[i][1] = b1; }
        }
        const float* W = g_d1T + (size_t)a * R_ * H_;
        for (int k = 0; k < R_; k += 4) {
            float4 hv[RT];
            #pragma unroll
            for (int i = 0; i < RT; i++)
                hv[i] = *reinterpret_cast<const float4*>(&enc_s[(ty + 16 * i) * ES + 96 + k]);
            #pragma unroll
            for (int kk = 0; kk < 4; kk++) {
                const float* Wr = W + (size_t)(k + kk) * H_;
                ull w0 = *reinterpret_cast<const ull*>(&Wr[cp]);
                ull w1 = *reinterpret_cast<const ull*>(&Wr[cp + 64]);
                #pragma unroll
                for (int i = 0; i < RT; i++) {
                    ull hh = dup2(reinterpret_cast<const float*>(&hv[i])[kk]);
                    acc[i][0] = fma2(hh, w0, acc[i][0]);
                    acc[i][1] = fma2(hh, w1, acc[i][1]);
                }
            }
        }
        #pragma unroll
        for (int i = 0; i < RT; i++) {
            int r = ty + 16 * i;
            #pragma unroll
            for (int jj = 0; jj < 2; jj++) {
                float2 v = unpk2(acc[i][jj]);
                v.x = fmaxf(v.x, 0.f); v.y = fmaxf(v.y, 0.f);
                *reinterpret_cast<ull*>(&d_s[r * DS + cp + 64 * jj]) = pack2(v.x, v.y);
            }
        }
    }
    __syncthreads();

    // ---- D2 (FFMA2) ----
    {
        ull acc[RT][2];
        {
            ull b0 = *reinterpret_cast<const ull*>(&d2b[a * H_ + cp]);
            ull b1 = *reinterpret_cast<const ull*>(&d2b[a * H_ + cp + 64]);
            #pragma unroll
            for (int i = 0; i < RT; i++) { acc[i][0] = b0; acc[i][1] = b1; }
        }
        const float* W = g_d2T + (size_t)a * H_ * H_;
        for (int k = 0; k < H_; k += 4) {
            float4 dv[RT];
            #pragma unroll
            for (int i = 0; i < RT; i++)
                dv[i] = *reinterpret_cast<const float4*>(&d_s[(ty + 16 * i) * DS + k]);
            #pragma unroll
            for (int kk = 0; kk < 4; kk++) {
                const float* Wr = W + (size_t)(k + kk) * H_;
                ull w0 = *reinterpret_cast<const ull*>(&Wr[cp]);
                ull w1 = *reinterpret_cast<const ull*>(&Wr[cp + 64]);
                #pragma unroll
                for (int i = 0; i < RT; i++) {
                    ull hh = dup2(reinterpret_cast<const float*>(&dv[i])[kk]);
                    acc[i][0] = fma2(hh, w0, acc[i][0]);
                    acc[i][1] = fma2(hh, w1, acc[i][1]);
                }
            }
        }
        #pragma unroll
        for (int i = 0; i < RT; i++) {
            int r = ty + 16 * i;
            #pragma unroll
            for (int jj = 0; jj < 2; jj++) {
                float2 v = unpk2(acc[i][jj]);
                v.x = fmaxf(v.x, 0.f); v.y = fmaxf(v.y, 0.f);
                *reinterpret_cast<ull*>(&e_s[r * DS + cp + 64 * jj]) = pack2(v.x, v.y);
            }
        }
    }
    __syncthreads();

    // ---- mean / std heads (exact math) ----
    for (int task = tid; task < nrows * 4; task += NTHREADS) {
        int r = task >> 2, o = task & 3;
        const float* W = (o < 2) ? (mw + ((size_t)a * 2 + o) * H_)
                                 : (sw + ((size_t)a * 2 + (o - 2)) * H_);
        float acc = (o < 2) ? mb[a * 2 + o] : sb[a * 2 + o - 2];
        for (int k = 0; k < H_; k++) acc += e_s[r * DS + k] * W[k];
        if (o >= 2)
            acc = fmaxf(acc, 0.f) + log1pf(expf(-fabsf(acc)));
        ms_s[r * 4 + o] = acc;
    }
    __syncthreads();

    // ---- per-row NLL + ev ----
    {
        double lsum = 0.0, esum = 0.0;
        if (tid < nrows) {
            int b = row0 + tid;
            size_t xb = (((size_t)(t + 1) * A_ + a) * B_ + b) * Y_ + 4 * a;
            float x0 = states[xb + 2], x1 = states[xb + 3];
            float m0 = ms_s[tid * 4 + 0], m1 = ms_s[tid * 4 + 1];
            float s0 = ms_s[tid * 4 + 2], s1 = ms_s[tid * 4 + 3];
            float z0 = (x0 - m0) / s0, z1 = (x1 - m1) / s1;
            const double L2PI = 1.8378770664093453;
            lsum = 0.5 * ((double)(z0 * z0) + (double)(z1 * z1)
                 + 2.0 * ((double)logf(s0) + (double)logf(s1)) + 2.0 * L2PI);
            float dm0 = m0 - x0, dm1 = m1 - x1;
            esum = sqrt((double)dm0 * dm0 + (double)dm1 * dm1);
        }
        #pragma unroll
        for (int o = 16; o; o >>= 1) {
            lsum += __shfl_down_sync(0xffffffffu, lsum, o);
            esum += __shfl_down_sync(0xffffffffu, esum, o);
        }
        if ((tid & 31) == 0) {
            atomicAdd(&g_acc[0], lsum);
            atomicAdd(&g_acc[2], esum);
        }
    }

    // ---- GRU via tf32 mma (R9 structure: m32-group, dist-1 rotation) ----
    {
        const int lane = tx;
        const int tg   = lane & 3;
        const int gid  = lane >> 2;
        #pragma unroll 1
        for (int u = 0; u < 6; u++) {
            int unit = ty + 16 * u;          // 0..95
            int mg = unit >> 5;              // 0..2
            int c  = unit & 31;
            int m0 = mg * 32;
            const bool two = (mg < 2);
            int j0 = c * 8;
            const float2* Wib = reinterpret_cast<const float2*>(
                g_Wim + ((size_t)(a * 32 + c) * NK8_I * 3) * 64);
            const float2* Whb = reinterpret_cast<const float2*>(
                g_Whm + ((size_t)(a * 32 + c) * NK8_H * 3) * 64);

            float acc0[6][4], acc1[6][4];
            {
                int jb = j0 + 2 * tg;
                float2 bv[6];
                bv[0] = *reinterpret_cast<const float2*>(&b_ih[a * G_ + jb]);
                bv[1] = *reinterpret_cast<const float2*>(&b_ih[a * G_ + 256 + jb]);
                bv[2] = *reinterpret_cast<const float2*>(&b_ih[a * G_ + 512 + jb]);
                bv[3] = *reinterpret_cast<const float2*>(&b_hh[a * G_ + jb]);
                bv[4] = *reinterpret_cast<const float2*>(&b_hh[a * G_ + 256 + jb]);
                bv[5] = *reinterpret_cast<const float2*>(&b_hh[a * G_ + 512 + jb]);
                #pragma unroll
                for (int g = 0; g < 6; g++) {
                    acc0[g][0] = bv[g].x; acc0[g][1] = bv[g].y;
                    acc0[g][2] = bv[g].x; acc0[g][3] = bv[g].y;
                    acc1[g][0] = bv[g].x; acc1[g][1] = bv[g].y;
                    acc1[g][2] = bv[g].x; acc1[g][3] = bv[g].y;
                }
            }

            // ---- y region: 12 k8, 3 gi gates ----
            {
                float2 w[3], wn[3];
                #pragma unroll
                for (int g = 0; g < 3; g++) w[g] = Wib[g * 32 + lane];
                for (int k8 = 0; k8 < 12; k8++) {
                    int k8n = (k8 < 11) ? k8 + 1 : 11;
                    #pragma unroll
                    for (int g = 0; g < 3; g++) wn[g] = Wib[(k8n * 3 + g) * 32 + lane];
                    int kc = k8 * 8 + tg;
                    unsigned A0[4];
                    A0[0] = __float_as_uint(enc_s[(m0 + gid) * ES + kc]);
                    A0[1] = __float_as_uint(enc_s[(m0 + gid + 8) * ES + kc]);
                    A0[2] = __float_as_uint(enc_s[(m0 + gid) * ES + kc + 4]);
                    A0[3] = __float_as_uint(enc_s[(m0 + gid + 8) * ES + kc + 4]);
                    #pragma unroll
                    for (int g = 0; g < 3; g++)
                        mma8(acc0[g], A0, __float_as_uint(w[g].x), __float_as_uint(w[g].y));
                    if (two) {
                        unsigned A1[4];
                        A1[0] = __float_as_uint(enc_s[(m0 + 16 + gid) * ES + kc]);
                        A1[1] = __float_as_uint(enc_s[(m0 + 24 + gid) * ES + kc]);
                        A1[2] = __float_as_uint(enc_s[(m0 + 16 + gid) * ES + kc + 4]);
                        A1[3] = __float_as_uint(enc_s[(m0 + 24 + gid) * ES + kc + 4]);
                        #pragma unroll
                        for (int g = 0; g < 3; g++)
                            mma8(acc1[g], A1, __float_as_uint(w[g].x), __float_as_uint(w[g].y));
                    }
                    #pragma unroll
                    for (int g = 0; g < 3; g++) w[g] = wn[g];
                }
            }

            // ---- h region: 32 k8, all 6 gates share the A fragment ----
            {
                float2 w[6], wn[6];
                #pragma unroll
                for (int g = 0; g < 3; g++) {
                    w[g]     = Wib[(12 * 3 + g) * 32 + lane];
                    w[3 + g] = Whb[g * 32 + lane];
                }
                for (int k8 = 0; k8 < 32; k8++) {
                    int k8n = (k8 < 31) ? k8 + 1 : 31;
                    #pragma unroll
                    for (int g = 0; g < 3; g++) {
                        wn[g]     = Wib[((12 + k8n) * 3 + g) * 32 + lane];
                        wn[3 + g] = Whb[(k8n * 3 + g) * 32 + lane];
                    }
                    int kc = 96 + k8 * 8 + tg;
                    unsigned A0[4];
                    A0[0] = __float_as_uint(enc_s[(m0 + gid) * ES + kc]);
                    A0[1] = __float_as_uint(enc_s[(m0 + gid + 8) * ES + kc]);
                    A0[2] = __float_as_uint(enc_s[(m0 + gid) * ES + kc + 4]);
                    A0[3] = __float_as_uint(enc_s[(m0 + gid + 8) * ES + kc + 4]);
                    #pragma unroll
                    for (int g = 0; g < 6; g++)
                        mma8(acc0[g], A0, __float_as_uint(w[g].x), __float_as_uint(w[g].y));
                    if (two) {
                        unsigned A1[4];
                        A1[0] = __float_as_uint(enc_s[(m0 + 16 + gid) * ES + kc]);
                        A1[1] = __float_as_uint(enc_s[(m0 + 24 + gid) * ES + kc]);
                        A1[2] = __float_as_uint(enc_s[(m0 + 16 + gid) * ES + kc + 4]);
                        A1[3] = __float_as_uint(enc_s[(m0 + 24 + gid) * ES + kc + 4]);
                        #pragma unroll
                        for (int g = 0; g < 6; g++)
                            mma8(acc1[g], A1, __float_as_uint(w[g].x), __float_as_uint(w[g].y));
                    }
                    #pragma unroll
                    for (int g = 0; g < 6; g++) w[g] = wn[g];
                }
            }

            // ---- epilogue: fast gates + h update ----
            #pragma unroll
            for (int tile = 0; tile < 2; tile++) {
                if (tile == 1 && !two) break;
                float (*ac)[4] = tile ? acc1 : acc0;
                int mt = m0 + 16 * tile;
                #pragma unroll
                for (int half = 0; half < 2; half++) {
                    int r = mt + gid + 8 * half;
                    int e0 = 2 * half, e1 = e0 + 1;
                    if (r < nrows) {
                        int jb = j0 + 2 * tg;
                        float* hrow = &g_h[((size_t)a * B_ + row0 + r) * R_ + jb];
                        float2 hold = *reinterpret_cast<const float2*>(hrow);
                        float rg0 = fsigmoid(ac[0][e0] + ac[3][e0]);
                        float rg1 = fsigmoid(ac[0][e1] + ac[3][e1]);
                        float zg0 = fsigmoid(ac[1][e0] + ac[4][e0]);
                        float zg1 = fsigmoid(ac[1][e1] + ac[4][e1]);
                        float ng0 = ftanh(ac[2][e0] + rg0 * ac[5][e0]);
                        float ng1 = ftanh(ac[2][e1] + rg1 * ac[5][e1]);
                        float h0 = (1.f - zg0) * ng0 + zg0 * hold.x;
                        float h1 = (1.f - zg1) * ng1 + zg1 * hold.y;
                        *reinterpret_cast<ull*>(hrow) = pack2(h0, h1);
                    }
                }
            }
        }
    }
}

__global__ void final_kernel(float* out) {
    if (threadIdx.x == 0) {
        const double denom = (double)T_ * A_;
        out[0] = (float)(g_acc[0] / denom);
        out[1] = (float)(g_acc[1] / denom);
        out[2] = (float)(g_acc[2] / denom);
    }
}

extern "C" void kernel_launch(void* const* d_in, const int* in_sizes, int n_in,
                              void* d_out, int out_size) {
    const float* states = (const float*)d_in[0];
    const float* W_ih   = (const float*)d_in[1];
    const float* W_hh   = (const float*)d_in[2];
    const float* b_ih   = (const float*)d_in[3];
    const float* b_hh   = (const float*)d_in[4];
    const float* d1w    = (const float*)d_in[5];
    const float* d1b    = (const float*)d_in[6];
    const float* d2w    = (const float*)d_in[7];
    const float* d2b    = (const float*)d_in[8];
    const float* mw     = (const float*)d_in[9];
    const float* mb     = (const float*)d_in[10];
    const float* sw     = (const float*)d_in[11];
    const float* sb     = (const float*)d_in[12];
    float* out = (float*)d_out;

    const size_t SMEM = (size_t)ROWPAD * (ES + DS + DS + 4) * sizeof(float); // 199,680 B
    cudaFuncSetAttribute(step_kernel, cudaFuncAttributeMaxDynamicSharedMemorySize, (int)SMEM);

    prep_kernel<<<1024, 256>>>(W_ih, W_hh, d1w, d2w);
    ep_kernel<<<(T_ * A_ * B_ + 255) / 256, 256>>>(states);

    dim3 grid(NTILES, A_);
    for (int t = 0; t < T_; t++) {
        step_kernel<<<grid, NTHREADS, SMEM>>>(states, b_ih, b_hh,
                                              d1b, d2b, mw, mb, sw, sb, t);
    }
    final_kernel<<<1, 32>>>(out);
}